// round 3
// baseline (speedup 1.0000x reference)
#include <cuda_runtime.h>
#include <cuda_fp16.h>

#define B_    128
#define IN_   1024
#define OUT_  1024

constexpr float BETA    = 0.99f;
constexpr float THRESH  = 1.0f;
constexpr float RESETV  = 0.8f;
constexpr float INV_TAU = 0.05f;              // 1/20
constexpr float A_SC    = 0.005f / 128.0f;    // A / B

// ---- device scratch (static, allocation-free) ------------------------------
__device__ float g_Wt[IN_ * OUT_];            // Wt[k][o] = W[o][k]
__device__ float g_part[4 * B_ * OUT_];       // k-split matmul partials
__device__ uint4 g_Ipk[B_ * IN_];             // (dp2, p2, q2, pad) broadcast half2
__device__ uint4 g_Opk[B_ * OUT_ / 2];        // per o-pair (df2, r2, -s2, pad)

__device__ __forceinline__ __half2 u2h(unsigned u) { return *reinterpret_cast<__half2*>(&u); }
__device__ __forceinline__ unsigned h2u(__half2 h) { return *reinterpret_cast<unsigned*>(&h); }

// ---------------------------------------------------------------------------
// Transpose W (OUT,IN) -> Wt (IN,OUT), 32x32 tiles.
// ---------------------------------------------------------------------------
__global__ __launch_bounds__(256) void k_transpose(const float* __restrict__ W)
{
    __shared__ float t[32][33];
    const int bx = blockIdx.x * 32;   // k range
    const int by = blockIdx.y * 32;   // o range
    const int tx = threadIdx.x, ty = threadIdx.y;  // (32, 8)
    #pragma unroll
    for (int i = 0; i < 32; i += 8)
        t[ty + i][tx] = W[(size_t)(by + ty + i) * IN_ + bx + tx];
    __syncthreads();
    #pragma unroll
    for (int i = 0; i < 32; i += 8)
        g_Wt[(size_t)(bx + ty + i) * OUT_ + by + tx] = t[tx][ty + i];
}

// ---------------------------------------------------------------------------
// Ipack: per (b,i) -> (dp, e^{dp/20}, e^{-dp/20}) broadcast into half2 lanes.
// ---------------------------------------------------------------------------
__global__ __launch_bounds__(256) void k_ipack(
    const float* __restrict__ spikes, const float* __restrict__ dpre)
{
    int idx = blockIdx.x * 256 + threadIdx.x;  // B_*IN_ threads
    float dp = (spikes[idx] > 0.0f) ? 0.0f : dpre[idx] + 1.0f;
    uint4 u;
    u.x = h2u(__float2half2_rn(dp));
    u.y = h2u(__float2half2_rn(__expf(dp * INV_TAU)));
    u.z = h2u(__float2half2_rn(__expf(-dp * INV_TAU)));
    u.w = 0;
    g_Ipk[idx] = u;
}

// ---------------------------------------------------------------------------
// Matmul partials: grid (16 b-blk, 4 o-blk, 4 kq). 256 threads.
// Block: 8 batches x 256 o x 256 k. Thread: 2 batches x 4 o (float4).
// W traffic: 256KB/block * 256 blocks = 64MB (L2-resident Wt).
// ---------------------------------------------------------------------------
__global__ __launch_bounds__(256) void k_matmul(const float* __restrict__ spikes)
{
    __shared__ float s[8][256];
    const int tid = threadIdx.x;
    const int bb0 = blockIdx.x * 8;
    const int ob  = blockIdx.y;          // o-block of 256
    const int kq  = blockIdx.z;          // k-quarter

    // stage 8 spike rows (k-quarter slice): 512 float4, 2 per thread
    {
        const float4* sp4 = reinterpret_cast<const float4*>(spikes);
        #pragma unroll
        for (int t = tid; t < 512; t += 256) {
            int b = t >> 6, k4 = t & 63;
            reinterpret_cast<float4*>(s)[t] = sp4[(bb0 + b) * 256 + kq * 64 + k4];
        }
    }
    __syncthreads();

    const int to = tid & 63;             // o float4 index within tile
    const int tb = tid >> 6;             // batch pair 0..3

    float4 acc0 = make_float4(0.f, 0.f, 0.f, 0.f);
    float4 acc1 = make_float4(0.f, 0.f, 0.f, 0.f);

    const float4* Wt4 = reinterpret_cast<const float4*>(g_Wt);
    const float* s0 = s[tb * 2];
    const float* s1 = s[tb * 2 + 1];

    #pragma unroll 4
    for (int k = 0; k < 256; k++) {
        float4 w = Wt4[(size_t)(kq * 256 + k) * 256 + ob * 64 + to];
        float a = s0[k], b = s1[k];
        acc0.x += w.x * a; acc0.y += w.y * a; acc0.z += w.z * a; acc0.w += w.w * a;
        acc1.x += w.x * b; acc1.y += w.y * b; acc1.z += w.z * b; acc1.w += w.w * b;
    }

    float4* P4 = reinterpret_cast<float4*>(g_part);
    P4[((kq * B_ + bb0 + tb * 2 + 0) * OUT_) / 4 + ob * 64 + to] = acc0;
    P4[((kq * B_ + bb0 + tb * 2 + 1) * OUT_) / 4 + ob * 64 + to] = acc1;
}

// ---------------------------------------------------------------------------
// LIF: reduce 4 partials, threshold/reset, spike+mem out, build Opack pairs.
// One thread per 4 outputs (2 o-pairs).
// ---------------------------------------------------------------------------
__global__ __launch_bounds__(256) void k_lif(
    const float* __restrict__ membrane, const float* __restrict__ dfire,
    float* __restrict__ out_spike, float* __restrict__ out_mem)
{
    int idx = blockIdx.x * 256 + threadIdx.x;     // B_*OUT_/4 threads
    int b = idx >> 8, o4 = idx & 255;
    int base = b * OUT_ + o4 * 4;

    float4 wsum = make_float4(0.f, 0.f, 0.f, 0.f);
    #pragma unroll
    for (int kq = 0; kq < 4; kq++) {
        float4 p = *reinterpret_cast<const float4*>(&g_part[(kq * B_ + b) * OUT_ + o4 * 4]);
        wsum.x += p.x; wsum.y += p.y; wsum.z += p.z; wsum.w += p.w;
    }
    float4 mem = *reinterpret_cast<const float4*>(&membrane[base]);
    float4 dfr = *reinterpret_cast<const float4*>(&dfire[base]);

    float m[4] = {mem.x * BETA + wsum.x, mem.y * BETA + wsum.y,
                  mem.z * BETA + wsum.z, mem.w * BETA + wsum.w};
    float d[4] = {dfr.x, dfr.y, dfr.z, dfr.w};
    float sp[4], df[4];
    #pragma unroll
    for (int j = 0; j < 4; j++) {
        sp[j] = (m[j] > THRESH) ? 1.0f : 0.0f;
        if (sp[j] > 0.f) m[j] -= RESETV;
        df[j] = (sp[j] > 0.f) ? 0.0f : d[j] + 1.0f;
    }

    *reinterpret_cast<float4*>(&out_spike[base]) = make_float4(sp[0], sp[1], sp[2], sp[3]);
    *reinterpret_cast<float4*>(&out_mem[base])   = make_float4(m[0], m[1], m[2], m[3]);

    #pragma unroll
    for (int pr = 0; pr < 2; pr++) {
        float f0 = df[pr * 2], f1 = df[pr * 2 + 1];
        uint4 u;
        u.x = h2u(__floats2half2_rn(f0, f1));
        u.y = h2u(__floats2half2_rn(__expf(-f0 * INV_TAU), __expf(-f1 * INV_TAU)));
        u.z = h2u(__floats2half2_rn(-__expf(f0 * INV_TAU), -__expf(f1 * INV_TAU)));
        u.w = 0;
        g_Opk[b * (OUT_ / 2) + o4 * 2 + pr] = u;
    }
}

// ---------------------------------------------------------------------------
// STDP: Delta[o,i] = avg_b [1(df>dp) e^{(dp-df)/20} - 1(df<dp) e^{(df-dp)/20}].
// Block: i-tile 32 (lane = one i, contiguous -> conflict-free LDS.128)
//        x o-tile 128 (warp owns 16 o = 8 pairs, broadcast LDS).
// grid (8 o-blk, 32 i-blk) = 256 blocks, 256 threads.
// Half2 accumulate per 16-batch chunk, flushed to fp32 (same numerics as R2).
// ---------------------------------------------------------------------------
__global__ __launch_bounds__(256) void k_stdp(
    const float* __restrict__ W, float* __restrict__ outW)
{
    __shared__ uint4 sI[16][32];   // 8 KB
    __shared__ uint4 sO[16][64];   // 16 KB

    const int tid = threadIdx.x;
    const int tx = tid & 31;       // lane -> i
    const int wp = tid >> 5;       // warp -> o-group of 16
    const int oBase = blockIdx.x * 128;
    const int iBase = blockIdx.y * 32;
    const int opBase = oBase >> 1;

    float accf[8][2];
    #pragma unroll
    for (int c = 0; c < 8; c++) { accf[c][0] = 0.f; accf[c][1] = 0.f; }

    for (int cb = 0; cb < 8; cb++) {           // 8 chunks of 16 batches
        #pragma unroll
        for (int t = tid; t < 16 * 32; t += 256) {
            int b = t >> 5, i = t & 31;
            sI[b][i] = g_Ipk[(cb * 16 + b) * IN_ + iBase + i];
        }
        #pragma unroll
        for (int t = tid; t < 16 * 64; t += 256) {
            int b = t >> 6, op = t & 63;
            sO[b][op] = g_Opk[(cb * 16 + b) * (OUT_ / 2) + opBase + op];
        }
        __syncthreads();

        __half2 acch[8];
        #pragma unroll
        for (int c = 0; c < 8; c++) acch[c] = __float2half2_rn(0.f);

        #pragma unroll 4
        for (int b = 0; b < 16; b++) {
            uint4 iv = sI[b][tx];              // conflict-free LDS.128
            __half2 dp2 = u2h(iv.x);
            __half2 p2  = u2h(iv.y);
            __half2 q2  = u2h(iv.z);
            #pragma unroll
            for (int c = 0; c < 8; c++) {
                uint4 ov = sO[b][wp * 8 + c];  // broadcast LDS.128
                __half2 df2 = u2h(ov.x);
                __half2 gt  = __hgt2(df2, dp2);          // 1.0 / 0.0
                __half2 lt  = __hlt2(df2, dp2);
                acch[c] = __hfma2(gt, __hmul2(p2, u2h(ov.y)), acch[c]);
                acch[c] = __hfma2(lt, __hmul2(q2, u2h(ov.z)), acch[c]);
            }
        }

        #pragma unroll
        for (int c = 0; c < 8; c++) {
            accf[c][0] += __low2float(acch[c]);
            accf[c][1] += __high2float(acch[c]);
        }
        __syncthreads();
    }

    // epilogue: newW[o][iBase+tx]; lanes along i -> 128B coalesced per warp
    const int i = iBase + tx;
    #pragma unroll
    for (int c = 0; c < 8; c++) {
        #pragma unroll
        for (int h = 0; h < 2; h++) {
            int o = oBase + wp * 16 + c * 2 + h;
            size_t off = (size_t)o * IN_ + i;
            outW[off] = W[off] + accf[c][h] * A_SC;
        }
    }
}

// ---------------------------------------------------------------------------
extern "C" void kernel_launch(void* const* d_in, const int* in_sizes, int n_in,
                              void* d_out, int out_size)
{
    const float* spikes   = (const float*)d_in[0];
    const float* W        = (const float*)d_in[1];
    const float* membrane = (const float*)d_in[2];
    const float* dpre     = (const float*)d_in[3];
    const float* dfire    = (const float*)d_in[4];

    float* out       = (float*)d_out;
    float* out_spike = out;                                   // (B, OUT)
    float* out_W     = out + B_ * OUT_;                       // (OUT, IN)
    float* out_mem   = out + B_ * OUT_ + (size_t)OUT_ * IN_;  // (B, OUT)

    k_transpose<<<dim3(32, 32), dim3(32, 8)>>>(W);
    k_ipack<<<(B_ * IN_) / 256, 256>>>(spikes, dpre);
    k_matmul<<<dim3(16, 4, 4), 256>>>(spikes);
    k_lif<<<(B_ * OUT_ / 4) / 256, 256>>>(membrane, dfire, out_spike, out_mem);
    k_stdp<<<dim3(8, 32), 256>>>(W, out_W);
}

// round 4
// speedup vs baseline: 1.3755x; 1.3755x over previous
#include <cuda_runtime.h>
#include <cuda_fp16.h>

#define B_    128
#define IN_   1024
#define OUT_  1024

constexpr float BETA    = 0.99f;
constexpr float THRESH  = 1.0f;
constexpr float RESETV  = 0.8f;
constexpr float INV_TAU = 0.05f;              // 1/20
constexpr float A_SC    = 0.005f / 128.0f;    // A / B

// ---- device scratch (static, allocation-free) ------------------------------
__device__ float g_Wt[IN_ * OUT_];            // Wt[k][o] = W[o][k]
__device__ float g_part[8 * B_ * OUT_];       // k-split matmul partials (8 splits)
__device__ uint4 g_Ipk[B_ * IN_];             // (dp2, p2, q2, pad) broadcast half2
__device__ uint4 g_Opk[B_ * OUT_ / 2];        // per o-pair (df2, r2, -s2, pad)

__device__ __forceinline__ __half2 u2h(unsigned u) { return *reinterpret_cast<__half2*>(&u); }
__device__ __forceinline__ unsigned h2u(__half2 h) { return *reinterpret_cast<unsigned*>(&h); }

// ---------------------------------------------------------------------------
// Front kernel: blocks [0,1024) transpose W -> Wt (32x32 tiles);
//               blocks [1024,1536) build Ipack. One launch, 256 threads each.
// ---------------------------------------------------------------------------
__global__ __launch_bounds__(256) void k_front(
    const float* __restrict__ W,
    const float* __restrict__ spikes,
    const float* __restrict__ dpre)
{
    if (blockIdx.x < 1024) {
        __shared__ float t[32][33];
        const int bx = (blockIdx.x & 31) * 32;   // k range
        const int by = (blockIdx.x >> 5) * 32;   // o range
        const int tx = threadIdx.x & 31;
        const int ty = threadIdx.x >> 5;         // 0..7
        #pragma unroll
        for (int i = 0; i < 32; i += 8)
            t[ty + i][tx] = W[(size_t)(by + ty + i) * IN_ + bx + tx];
        __syncthreads();
        #pragma unroll
        for (int i = 0; i < 32; i += 8)
            g_Wt[(size_t)(bx + ty + i) * OUT_ + by + tx] = t[tx][ty + i];
    } else {
        int idx = (blockIdx.x - 1024) * 256 + threadIdx.x;  // B_*IN_
        float dp = (spikes[idx] > 0.0f) ? 0.0f : dpre[idx] + 1.0f;
        uint4 u;
        u.x = h2u(__float2half2_rn(dp));
        u.y = h2u(__float2half2_rn(__expf(dp * INV_TAU)));
        u.z = h2u(__float2half2_rn(__expf(-dp * INV_TAU)));
        u.w = 0;
        g_Ipk[idx] = u;
    }
}

// ---------------------------------------------------------------------------
// Matmul partials: grid (16 b-blk, 8 k-eighth). 256 threads.
// Block: 8 batches x 1024 o x 128 k. Thread: 8 batches x 1 o-float4.
// Phase ratio: 8 broadcast LDS + 1 LDG.128 per 1024 FMA-lanes per warp-k.
// ---------------------------------------------------------------------------
__global__ __launch_bounds__(256) void k_matmul(const float* __restrict__ spikes)
{
    __shared__ float s[8][128];
    const int tid = threadIdx.x;
    const int bb0 = blockIdx.x * 8;
    const int kq  = blockIdx.y;          // k-eighth (128 k)

    // stage 8 spike rows (128-k slice): 256 float4, 1 per thread
    {
        const float4* sp4 = reinterpret_cast<const float4*>(spikes);
        int b = tid >> 5, k4 = tid & 31;
        reinterpret_cast<float4*>(s)[tid] = sp4[(bb0 + b) * 256 + kq * 32 + k4];
    }
    __syncthreads();

    float4 acc[8];
    #pragma unroll
    for (int b = 0; b < 8; b++) acc[b] = make_float4(0.f, 0.f, 0.f, 0.f);

    const float4* Wt4 = reinterpret_cast<const float4*>(g_Wt);
    #pragma unroll 2
    for (int k = 0; k < 128; k++) {
        float4 w = Wt4[(size_t)(kq * 128 + k) * 256 + tid];   // coalesced 512B/warp
        #pragma unroll
        for (int b = 0; b < 8; b++) {
            float sv = s[b][k];          // broadcast
            acc[b].x += w.x * sv; acc[b].y += w.y * sv;
            acc[b].z += w.z * sv; acc[b].w += w.w * sv;
        }
    }

    float4* P4 = reinterpret_cast<float4*>(g_part);
    #pragma unroll
    for (int b = 0; b < 8; b++)
        P4[((kq * B_ + bb0 + b) * OUT_) / 4 + tid] = acc[b];
}

// ---------------------------------------------------------------------------
// LIF: reduce 8 partials, threshold/reset, spike+mem out, build Opack pairs.
// One thread per o-pair (R2 structure).
// ---------------------------------------------------------------------------
__global__ __launch_bounds__(256) void k_lif(
    const float* __restrict__ membrane, const float* __restrict__ dfire,
    float* __restrict__ out_spike, float* __restrict__ out_mem)
{
    int idx = blockIdx.x * 256 + threadIdx.x;     // B_*OUT_/2
    int b = idx >> 9, opi = idx & 511;
    int base = b * OUT_ + opi * 2;

    float w0 = 0.f, w1 = 0.f;
    #pragma unroll
    for (int kq = 0; kq < 8; kq++) {
        float2 p = *reinterpret_cast<const float2*>(&g_part[(kq * B_ + b) * OUT_ + opi * 2]);
        w0 += p.x; w1 += p.y;
    }
    float2 mem = *reinterpret_cast<const float2*>(&membrane[base]);
    float2 dfr = *reinterpret_cast<const float2*>(&dfire[base]);

    float m0 = mem.x * BETA + w0, m1 = mem.y * BETA + w1;
    float s0 = (m0 > THRESH) ? 1.0f : 0.0f;
    float s1 = (m1 > THRESH) ? 1.0f : 0.0f;
    if (s0 > 0.f) m0 -= RESETV;
    if (s1 > 0.f) m1 -= RESETV;

    *reinterpret_cast<float2*>(&out_spike[base]) = make_float2(s0, s1);
    *reinterpret_cast<float2*>(&out_mem[base])   = make_float2(m0, m1);

    float df0 = (s0 > 0.f) ? 0.0f : dfr.x + 1.0f;
    float df1 = (s1 > 0.f) ? 0.0f : dfr.y + 1.0f;
    uint4 u;
    u.x = h2u(__floats2half2_rn(df0, df1));
    u.y = h2u(__floats2half2_rn(__expf(-df0 * INV_TAU), __expf(-df1 * INV_TAU)));
    u.z = h2u(__floats2half2_rn(-__expf(df0 * INV_TAU), -__expf(df1 * INV_TAU)));
    u.w = 0;
    g_Opk[b * (OUT_ / 2) + opi] = u;
}

// ---------------------------------------------------------------------------
// STDP (R2 structure, iv bank-conflict fixed):
// Block tile 64 i x 64 o, grid (16,16). Thread: 2 i (at j*32+tx -> contiguous,
// conflict-free LDS.128) x 8 o (4 half2 pairs, broadcast LDS).
// Half2 accumulate per 16-batch chunk, flushed to fp32 (R2 numerics).
// ---------------------------------------------------------------------------
__global__ __launch_bounds__(256) void k_stdp(
    const float* __restrict__ W, float* __restrict__ outW)
{
    __shared__ uint4 sI[16][64];   // 16 KB
    __shared__ uint4 sO[16][32];   // 8 KB

    const int tid = threadIdx.x;
    const int tx = tid & 31;
    const int ty = tid >> 5;       // o-octet 0..7
    const int oBase = blockIdx.x * 64;
    const int iBase = blockIdx.y * 64;
    const int opBase = oBase >> 1;

    float accf[2][4][2];
    #pragma unroll
    for (int j = 0; j < 2; j++)
        #pragma unroll
        for (int c = 0; c < 4; c++) { accf[j][c][0] = 0.f; accf[j][c][1] = 0.f; }

    for (int cb = 0; cb < 8; cb++) {           // 8 chunks of 16 batches
        #pragma unroll
        for (int t = tid; t < 16 * 64; t += 256) {
            int b = t >> 6, i = t & 63;
            sI[b][i] = g_Ipk[(cb * 16 + b) * IN_ + iBase + i];
        }
        #pragma unroll
        for (int t = tid; t < 16 * 32; t += 256) {
            int b = t >> 5, op = t & 31;
            sO[b][op] = g_Opk[(cb * 16 + b) * (OUT_ / 2) + opBase + op];
        }
        __syncthreads();

        __half2 acch[2][4];
        #pragma unroll
        for (int j = 0; j < 2; j++)
            #pragma unroll
            for (int c = 0; c < 4; c++) acch[j][c] = __float2half2_rn(0.f);

        #pragma unroll 4
        for (int b = 0; b < 16; b++) {
            uint4 iv[2], ov[4];
            #pragma unroll
            for (int j = 0; j < 2; j++) iv[j] = sI[b][j * 32 + tx];  // conflict-free
            #pragma unroll
            for (int c = 0; c < 4; c++) ov[c] = sO[b][ty * 4 + c];   // broadcast

            #pragma unroll
            for (int j = 0; j < 2; j++) {
                __half2 dp2 = u2h(iv[j].x);
                __half2 p2  = u2h(iv[j].y);
                __half2 q2  = u2h(iv[j].z);
                #pragma unroll
                for (int c = 0; c < 4; c++) {
                    __half2 df2 = u2h(ov[c].x);
                    __half2 gt  = __hgt2(df2, dp2);       // 1.0 / 0.0
                    __half2 lt  = __hlt2(df2, dp2);
                    acch[j][c] = __hfma2(gt, __hmul2(p2, u2h(ov[c].y)), acch[j][c]);
                    acch[j][c] = __hfma2(lt, __hmul2(q2, u2h(ov[c].z)), acch[j][c]);
                }
            }
        }

        #pragma unroll
        for (int j = 0; j < 2; j++)
            #pragma unroll
            for (int c = 0; c < 4; c++) {
                accf[j][c][0] += __low2float(acch[j][c]);
                accf[j][c][1] += __high2float(acch[j][c]);
            }
        __syncthreads();
    }

    // epilogue: lanes along i (contiguous) -> coalesced 128B per warp-store
    #pragma unroll
    for (int j = 0; j < 2; j++) {
        const int i = iBase + j * 32 + tx;
        #pragma unroll
        for (int c = 0; c < 4; c++) {
            #pragma unroll
            for (int h = 0; h < 2; h++) {
                int o = oBase + ty * 8 + c * 2 + h;
                size_t off = (size_t)o * IN_ + i;
                outW[off] = W[off] + accf[j][c][h] * A_SC;
            }
        }
    }
}

// ---------------------------------------------------------------------------
extern "C" void kernel_launch(void* const* d_in, const int* in_sizes, int n_in,
                              void* d_out, int out_size)
{
    const float* spikes   = (const float*)d_in[0];
    const float* W        = (const float*)d_in[1];
    const float* membrane = (const float*)d_in[2];
    const float* dpre     = (const float*)d_in[3];
    const float* dfire    = (const float*)d_in[4];

    float* out       = (float*)d_out;
    float* out_spike = out;                                   // (B, OUT)
    float* out_W     = out + B_ * OUT_;                       // (OUT, IN)
    float* out_mem   = out + B_ * OUT_ + (size_t)OUT_ * IN_;  // (B, OUT)

    k_front<<<1536, 256>>>(W, spikes, dpre);
    k_matmul<<<dim3(16, 8), 256>>>(spikes);
    k_lif<<<(B_ * OUT_ / 2) / 256, 256>>>(membrane, dfire, out_spike, out_mem);
    k_stdp<<<dim3(16, 16), 256>>>(W, out_W);
}

// round 5
// speedup vs baseline: 1.8340x; 1.3333x over previous
#include <cuda_runtime.h>
#include <cuda_fp16.h>

#define B_    128
#define IN_   1024
#define OUT_  1024

constexpr float BETA    = 0.99f;
constexpr float THRESH  = 1.0f;
constexpr float RESETV  = 0.8f;
constexpr float INV_TAU = 0.05f;              // 1/20
constexpr float A_SC    = 0.005f / 128.0f;    // A / B

// ---- device scratch (static, allocation-free) ------------------------------
__device__ float g_Wt[IN_ * OUT_];            // Wt[k][o] = W[o][k]
__device__ float g_part[16 * B_ * OUT_];      // k-split matmul partials (16)
__device__ uint2 g_Ipk[B_ * IN_];             // (p2, q2): e^{+dp/20}, e^{-dp/20} broadcast
__device__ uint2 g_Opk[B_ * OUT_ / 2];        // per o-pair (r2, -s2): e^{-df/20}, -e^{+df/20}

__device__ __forceinline__ __half2 u2h(unsigned u) { return *reinterpret_cast<__half2*>(&u); }
__device__ __forceinline__ unsigned h2u(__half2 h) { return *reinterpret_cast<unsigned*>(&h); }

// ---------------------------------------------------------------------------
// Front kernel: blocks [0,1024) transpose W -> Wt; blocks [1024,1536) Ipack.
// ---------------------------------------------------------------------------
__global__ __launch_bounds__(256) void k_front(
    const float* __restrict__ W,
    const float* __restrict__ spikes,
    const float* __restrict__ dpre)
{
    if (blockIdx.x < 1024) {
        __shared__ float t[32][33];
        const int bx = (blockIdx.x & 31) * 32;   // k range
        const int by = (blockIdx.x >> 5) * 32;   // o range
        const int tx = threadIdx.x & 31;
        const int ty = threadIdx.x >> 5;         // 0..7
        #pragma unroll
        for (int i = 0; i < 32; i += 8)
            t[ty + i][tx] = W[(size_t)(by + ty + i) * IN_ + bx + tx];
        __syncthreads();
        #pragma unroll
        for (int i = 0; i < 32; i += 8)
            g_Wt[(size_t)(bx + ty + i) * OUT_ + by + tx] = t[tx][ty + i];
    } else {
        int idx = (blockIdx.x - 1024) * 256 + threadIdx.x;  // B_*IN_
        float dp = (spikes[idx] > 0.0f) ? 0.0f : dpre[idx] + 1.0f;
        uint2 u;
        u.x = h2u(__float2half2_rn(__expf(dp * INV_TAU)));   // p (broadcast pair)
        u.y = h2u(__float2half2_rn(__expf(-dp * INV_TAU)));  // q
        g_Ipk[idx] = u;
    }
}

// ---------------------------------------------------------------------------
// Matmul partials: grid (16 b-blk of 8, 16 kq of 64). 256 threads.
// Thread: 8 batches x 1 o-float4. W traffic = 16 * 4MB = 64MB (L2-resident).
// ---------------------------------------------------------------------------
__global__ __launch_bounds__(256) void k_matmul(const float* __restrict__ spikes)
{
    __shared__ float s[8][64];
    const int tid = threadIdx.x;
    const int bb0 = blockIdx.x * 8;
    const int kq  = blockIdx.y;          // k-chunk of 64

    // stage 8 spike rows (64-k slice): 128 float4
    if (tid < 128) {
        const float4* sp4 = reinterpret_cast<const float4*>(spikes);
        int b = tid >> 4, k4 = tid & 15;
        reinterpret_cast<float4*>(s)[tid] = sp4[(bb0 + b) * 256 + kq * 16 + k4];
    }
    __syncthreads();

    float4 acc[8];
    #pragma unroll
    for (int b = 0; b < 8; b++) acc[b] = make_float4(0.f, 0.f, 0.f, 0.f);

    const float4* Wt4 = reinterpret_cast<const float4*>(g_Wt);
    #pragma unroll 2
    for (int k = 0; k < 64; k++) {
        float4 w = Wt4[(size_t)(kq * 64 + k) * 256 + tid];   // coalesced
        #pragma unroll
        for (int b = 0; b < 8; b++) {
            float sv = s[b][k];          // broadcast
            acc[b].x += w.x * sv; acc[b].y += w.y * sv;
            acc[b].z += w.z * sv; acc[b].w += w.w * sv;
        }
    }

    float4* P4 = reinterpret_cast<float4*>(g_part);
    #pragma unroll
    for (int b = 0; b < 8; b++)
        P4[((kq * B_ + bb0 + b) * OUT_) / 4 + tid] = acc[b];
}

// ---------------------------------------------------------------------------
// LIF: reduce 16 partials, threshold/reset, spike+mem out, Opack (uint2/pair).
// ---------------------------------------------------------------------------
__global__ __launch_bounds__(256) void k_lif(
    const float* __restrict__ membrane, const float* __restrict__ dfire,
    float* __restrict__ out_spike, float* __restrict__ out_mem)
{
    int idx = blockIdx.x * 256 + threadIdx.x;     // B_*OUT_/2
    int b = idx >> 9, opi = idx & 511;
    int base = b * OUT_ + opi * 2;

    float w0 = 0.f, w1 = 0.f;
    #pragma unroll
    for (int kq = 0; kq < 16; kq++) {
        float2 p = *reinterpret_cast<const float2*>(&g_part[(kq * B_ + b) * OUT_ + opi * 2]);
        w0 += p.x; w1 += p.y;
    }
    float2 mem = *reinterpret_cast<const float2*>(&membrane[base]);
    float2 dfr = *reinterpret_cast<const float2*>(&dfire[base]);

    float m0 = mem.x * BETA + w0, m1 = mem.y * BETA + w1;
    float s0 = (m0 > THRESH) ? 1.0f : 0.0f;
    float s1 = (m1 > THRESH) ? 1.0f : 0.0f;
    if (s0 > 0.f) m0 -= RESETV;
    if (s1 > 0.f) m1 -= RESETV;

    *reinterpret_cast<float2*>(&out_spike[base]) = make_float2(s0, s1);
    *reinterpret_cast<float2*>(&out_mem[base])   = make_float2(m0, m1);

    float df0 = (s0 > 0.f) ? 0.0f : dfr.x + 1.0f;
    float df1 = (s1 > 0.f) ? 0.0f : dfr.y + 1.0f;
    uint2 u;
    u.x = h2u(__floats2half2_rn(__expf(-df0 * INV_TAU), __expf(-df1 * INV_TAU)));  // r
    u.y = h2u(__floats2half2_rn(-__expf(df0 * INV_TAU), -__expf(df1 * INV_TAU))); // -s
    g_Opk[b * (OUT_ / 2) + opi] = u;
}

// ---------------------------------------------------------------------------
// STDP via product-vs-1 test (no df/dp in inner loop):
//   t1 = p*r = e^{(dp-df)/20}: contributes +t1 iff t1 < 1  (<=> df > dp)
//   t2 = q*(-s) = -e^{(df-dp)/20}: contributes t2 iff t2 > -1 (<=> df < dp)
//   dp==df==0 (both spiked): t1 = 1, t2 = -1 -> exactly zero. Correct.
// Tile 32i x 32o, grid (32 o-blk, 32 i-blk) = 1024 blocks, 256 threads.
// Thread: 1 i (lane) x 4 o (2 half2 pairs, one uint4 broadcast).
// ---------------------------------------------------------------------------
__global__ __launch_bounds__(256) void k_stdp(
    const float* __restrict__ W, float* __restrict__ outW)
{
    __shared__ uint2 sI[16][32];   // 4 KB
    __shared__ uint4 sO[16][8];    // 2 KB

    const int tid = threadIdx.x;
    const int tx = tid & 31;       // lane -> i
    const int wp = tid >> 5;       // warp -> o-quad
    const int oBase = blockIdx.x * 32;
    const int iBase = blockIdx.y * 32;

    const __half2 ONE  = __float2half2_rn(1.0f);
    const __half2 NEG1 = __float2half2_rn(-1.0f);

    float accf[2][2];
    accf[0][0] = accf[0][1] = accf[1][0] = accf[1][1] = 0.f;

    const uint4* Ipk4 = reinterpret_cast<const uint4*>(g_Ipk);
    const uint4* Opk4 = reinterpret_cast<const uint4*>(g_Opk);

    for (int cb = 0; cb < 8; cb++) {           // 8 chunks of 16 batches
        // stage sI: 16 b x 32 uint2 = 256 uint4; one per thread
        {
            int b = tid >> 4, j = tid & 15;
            reinterpret_cast<uint4*>(sI)[tid] =
                Ipk4[((cb * 16 + b) * IN_ + iBase) / 2 + j];
        }
        // stage sO: 16 b x 16 uint2 = 128 uint4
        if (tid < 128) {
            int b = tid >> 3, j = tid & 7;
            reinterpret_cast<uint4*>(sO)[tid] =
                Opk4[(cb * 16 + b) * (OUT_ / 4) + (oBase >> 2) + j];
        }
        __syncthreads();

        __half2 acch[2];
        acch[0] = __float2half2_rn(0.f);
        acch[1] = __float2half2_rn(0.f);

        #pragma unroll 4
        for (int b = 0; b < 16; b++) {
            uint2 iv = sI[b][tx];              // LDS.64 conflict-free
            uint4 ov = sO[b][wp];              // LDS.128 broadcast
            __half2 p2 = u2h(iv.x);
            __half2 q2 = u2h(iv.y);
            {
                __half2 t1 = __hmul2(p2, u2h(ov.x));
                __half2 t2 = __hmul2(q2, u2h(ov.y));
                __half2 m1 = __hlt2(t1, ONE);
                __half2 m2 = __hgt2(t2, NEG1);
                acch[0] = __hfma2(m1, t1, acch[0]);
                acch[0] = __hfma2(m2, t2, acch[0]);
            }
            {
                __half2 t1 = __hmul2(p2, u2h(ov.z));
                __half2 t2 = __hmul2(q2, u2h(ov.w));
                __half2 m1 = __hlt2(t1, ONE);
                __half2 m2 = __hgt2(t2, NEG1);
                acch[1] = __hfma2(m1, t1, acch[1]);
                acch[1] = __hfma2(m2, t2, acch[1]);
            }
        }

        accf[0][0] += __low2float(acch[0]);
        accf[0][1] += __high2float(acch[0]);
        accf[1][0] += __low2float(acch[1]);
        accf[1][1] += __high2float(acch[1]);
        __syncthreads();
    }

    // epilogue: newW[o][i], lanes along i -> 128B coalesced per warp-store
    const int i = iBase + tx;
    #pragma unroll
    for (int c = 0; c < 2; c++) {
        #pragma unroll
        for (int h = 0; h < 2; h++) {
            int o = oBase + wp * 4 + c * 2 + h;
            size_t off = (size_t)o * IN_ + i;
            outW[off] = W[off] + accf[c][h] * A_SC;
        }
    }
}

// ---------------------------------------------------------------------------
extern "C" void kernel_launch(void* const* d_in, const int* in_sizes, int n_in,
                              void* d_out, int out_size)
{
    const float* spikes   = (const float*)d_in[0];
    const float* W        = (const float*)d_in[1];
    const float* membrane = (const float*)d_in[2];
    const float* dpre     = (const float*)d_in[3];
    const float* dfire    = (const float*)d_in[4];

    float* out       = (float*)d_out;
    float* out_spike = out;                                   // (B, OUT)
    float* out_W     = out + B_ * OUT_;                       // (OUT, IN)
    float* out_mem   = out + B_ * OUT_ + (size_t)OUT_ * IN_;  // (B, OUT)

    k_front<<<1536, 256>>>(W, spikes, dpre);
    k_matmul<<<dim3(16, 16), 256>>>(spikes);
    k_lif<<<(B_ * OUT_ / 2) / 256, 256>>>(membrane, dfire, out_spike, out_mem);
    k_stdp<<<dim3(32, 32), 256>>>(W, out_W);
}

// round 6
// speedup vs baseline: 1.9079x; 1.0403x over previous
#include <cuda_runtime.h>
#include <cuda_fp16.h>

#define B_    128
#define IN_   1024
#define OUT_  1024

constexpr float BETA    = 0.99f;
constexpr float THRESH  = 1.0f;
constexpr float RESETV  = 0.8f;
constexpr float INV_TAU = 0.05f;              // 1/20
constexpr float A_SC    = 0.005f / 128.0f;    // A / B

// ---- device scratch (static, allocation-free) ------------------------------
__device__ float g_Wt[IN_ * OUT_];            // Wt[k][o] = W[o][k]
__device__ float g_part[16 * B_ * OUT_];      // k-split matmul partials (16)
// Ipk slot layout: within each 64-i group g, i=(g*64+r) stored at slot
// g*64 + (r&31)*2 + (r>>5)  ->  (i, i+32) are adjacent uint2 = one uint4.
__device__ uint2 g_Ipk[B_ * IN_];             // (p2, q2): e^{+dp/20}, e^{-dp/20}
__device__ uint2 g_Opk[B_ * OUT_ / 2];        // per o-pair (r2, -s2)

__device__ __forceinline__ __half2 u2h(unsigned u) { return *reinterpret_cast<__half2*>(&u); }
__device__ __forceinline__ unsigned h2u(__half2 h) { return *reinterpret_cast<unsigned*>(&h); }

// ---------------------------------------------------------------------------
// Front kernel: blocks [0,1024) transpose W -> Wt; blocks [1024,1536) Ipack.
// ---------------------------------------------------------------------------
__global__ __launch_bounds__(256) void k_front(
    const float* __restrict__ W,
    const float* __restrict__ spikes,
    const float* __restrict__ dpre)
{
    if (blockIdx.x < 1024) {
        __shared__ float t[32][33];
        const int bx = (blockIdx.x & 31) * 32;   // k range
        const int by = (blockIdx.x >> 5) * 32;   // o range
        const int tx = threadIdx.x & 31;
        const int ty = threadIdx.x >> 5;         // 0..7
        #pragma unroll
        for (int i = 0; i < 32; i += 8)
            t[ty + i][tx] = W[(size_t)(by + ty + i) * IN_ + bx + tx];
        __syncthreads();
        #pragma unroll
        for (int i = 0; i < 32; i += 8)
            g_Wt[(size_t)(bx + ty + i) * OUT_ + by + tx] = t[tx][ty + i];
    } else {
        int idx = (blockIdx.x - 1024) * 256 + threadIdx.x;  // b*IN_ + i
        float dp = (spikes[idx] > 0.0f) ? 0.0f : dpre[idx] + 1.0f;
        uint2 u;
        u.x = h2u(__float2half2_rn(__expf(dp * INV_TAU)));   // p pair
        u.y = h2u(__float2half2_rn(__expf(-dp * INV_TAU)));  // q pair
        int i = idx & (IN_ - 1);
        int b = idx >> 10;
        int g = i >> 6, r = i & 63;
        int slot = (g << 6) + ((r & 31) << 1) + (r >> 5);
        g_Ipk[b * IN_ + slot] = u;
    }
}

// ---------------------------------------------------------------------------
// Matmul partials: grid (16 b-blk of 8, 16 kq of 64). 256 threads.
// Thread: 8 batches x 1 o-float4.
// ---------------------------------------------------------------------------
__global__ __launch_bounds__(256) void k_matmul(const float* __restrict__ spikes)
{
    __shared__ float s[8][64];
    const int tid = threadIdx.x;
    const int bb0 = blockIdx.x * 8;
    const int kq  = blockIdx.y;          // k-chunk of 64

    if (tid < 128) {
        const float4* sp4 = reinterpret_cast<const float4*>(spikes);
        int b = tid >> 4, k4 = tid & 15;
        reinterpret_cast<float4*>(s)[tid] = sp4[(bb0 + b) * 256 + kq * 16 + k4];
    }
    __syncthreads();

    float4 acc[8];
    #pragma unroll
    for (int b = 0; b < 8; b++) acc[b] = make_float4(0.f, 0.f, 0.f, 0.f);

    const float4* Wt4 = reinterpret_cast<const float4*>(g_Wt);
    #pragma unroll 2
    for (int k = 0; k < 64; k++) {
        float4 w = Wt4[(size_t)(kq * 64 + k) * 256 + tid];   // coalesced
        #pragma unroll
        for (int b = 0; b < 8; b++) {
            float sv = s[b][k];          // broadcast
            acc[b].x += w.x * sv; acc[b].y += w.y * sv;
            acc[b].z += w.z * sv; acc[b].w += w.w * sv;
        }
    }

    float4* P4 = reinterpret_cast<float4*>(g_part);
    #pragma unroll
    for (int b = 0; b < 8; b++)
        P4[((kq * B_ + bb0 + b) * OUT_) / 4 + tid] = acc[b];
}

// ---------------------------------------------------------------------------
// LIF: reduce 16 partials, threshold/reset, spike+mem out, Opack (uint2/pair).
// ---------------------------------------------------------------------------
__global__ __launch_bounds__(256) void k_lif(
    const float* __restrict__ membrane, const float* __restrict__ dfire,
    float* __restrict__ out_spike, float* __restrict__ out_mem)
{
    int idx = blockIdx.x * 256 + threadIdx.x;     // B_*OUT_/2
    int b = idx >> 9, opi = idx & 511;
    int base = b * OUT_ + opi * 2;

    float w0 = 0.f, w1 = 0.f;
    #pragma unroll
    for (int kq = 0; kq < 16; kq++) {
        float2 p = *reinterpret_cast<const float2*>(&g_part[(kq * B_ + b) * OUT_ + opi * 2]);
        w0 += p.x; w1 += p.y;
    }
    float2 mem = *reinterpret_cast<const float2*>(&membrane[base]);
    float2 dfr = *reinterpret_cast<const float2*>(&dfire[base]);

    float m0 = mem.x * BETA + w0, m1 = mem.y * BETA + w1;
    float s0 = (m0 > THRESH) ? 1.0f : 0.0f;
    float s1 = (m1 > THRESH) ? 1.0f : 0.0f;
    if (s0 > 0.f) m0 -= RESETV;
    if (s1 > 0.f) m1 -= RESETV;

    *reinterpret_cast<float2*>(&out_spike[base]) = make_float2(s0, s1);
    *reinterpret_cast<float2*>(&out_mem[base])   = make_float2(m0, m1);

    float df0 = (s0 > 0.f) ? 0.0f : dfr.x + 1.0f;
    float df1 = (s1 > 0.f) ? 0.0f : dfr.y + 1.0f;
    uint2 u;
    u.x = h2u(__floats2half2_rn(__expf(-df0 * INV_TAU), __expf(-df1 * INV_TAU)));  // r
    u.y = h2u(__floats2half2_rn(-__expf(df0 * INV_TAU), -__expf(df1 * INV_TAU))); // -s
    g_Opk[b * (OUT_ / 2) + opi] = u;
}

// ---------------------------------------------------------------------------
// STDP via product-vs-1 test:
//   t1 = p*r < 1  <=> df > dp : contribute +t1
//   t2 = q*(-s) > -1 <=> df < dp : contribute t2
//   dp==df -> t1==1, t2==-1 -> exactly zero.
// Tile 64i x 32o, grid (32 o-blk, 16 i-blk) = 512 blocks, 256 threads.
// Thread: 2 i (one interleaved uint4 from sI) x 4 o (one uint4 broadcast).
// ---------------------------------------------------------------------------
__global__ __launch_bounds__(256) void k_stdp(
    const float* __restrict__ W, float* __restrict__ outW)
{
    __shared__ uint4 sI[16][32];   // 8 KB: (p,q) for i=j and i=j+32
    __shared__ uint4 sO[16][8];    // 2 KB: o-quads

    const int tid = threadIdx.x;
    const int tx = tid & 31;       // lane -> i (and i+32)
    const int wp = tid >> 5;       // warp -> o-quad
    const int oBase = blockIdx.x * 32;
    const int iBase = blockIdx.y * 64;

    const __half2 ONE  = __float2half2_rn(1.0f);
    const __half2 NEG1 = __float2half2_rn(-1.0f);

    float accf[2][2][2];           // [i-half][o-pair][lo/hi]
    #pragma unroll
    for (int j = 0; j < 2; j++)
        #pragma unroll
        for (int c = 0; c < 2; c++) { accf[j][c][0] = 0.f; accf[j][c][1] = 0.f; }

    const uint4* Ipk4 = reinterpret_cast<const uint4*>(g_Ipk);
    const uint4* Opk4 = reinterpret_cast<const uint4*>(g_Opk);

    for (int cb = 0; cb < 8; cb++) {           // 8 chunks of 16 batches
        // sI: 16 b x 32 uint4 = 512; 2 per thread, coalesced LDG.128
        #pragma unroll
        for (int t = tid; t < 512; t += 256) {
            int b = t >> 5, j = t & 31;
            sI[b][j] = Ipk4[((cb * 16 + b) * IN_ + iBase) / 2 + j];
        }
        // sO: 16 b x 8 uint4 = 128
        if (tid < 128) {
            int b = tid >> 3, j = tid & 7;
            sO[b][j] = Opk4[(cb * 16 + b) * (OUT_ / 4) + (oBase >> 2) + j];
        }
        __syncthreads();

        __half2 acch[2][2];
        #pragma unroll
        for (int j = 0; j < 2; j++) {
            acch[j][0] = __float2half2_rn(0.f);
            acch[j][1] = __float2half2_rn(0.f);
        }

        #pragma unroll 4
        for (int b = 0; b < 16; b++) {
            uint4 iv = sI[b][tx];              // LDS.128 conflict-free
            uint4 ov = sO[b][wp];              // LDS.128 broadcast
            __half2 pq[2][2] = {{u2h(iv.x), u2h(iv.y)}, {u2h(iv.z), u2h(iv.w)}};
            __half2 rs[2][2] = {{u2h(ov.x), u2h(ov.y)}, {u2h(ov.z), u2h(ov.w)}};
            #pragma unroll
            for (int j = 0; j < 2; j++) {      // i-half
                #pragma unroll
                for (int c = 0; c < 2; c++) {  // o-pair
                    __half2 t1 = __hmul2(pq[j][0], rs[c][0]);
                    __half2 t2 = __hmul2(pq[j][1], rs[c][1]);
                    __half2 m1 = __hlt2(t1, ONE);
                    __half2 m2 = __hgt2(t2, NEG1);
                    acch[j][c] = __hfma2(m1, t1, acch[j][c]);
                    acch[j][c] = __hfma2(m2, t2, acch[j][c]);
                }
            }
        }

        #pragma unroll
        for (int j = 0; j < 2; j++)
            #pragma unroll
            for (int c = 0; c < 2; c++) {
                accf[j][c][0] += __low2float(acch[j][c]);
                accf[j][c][1] += __high2float(acch[j][c]);
            }
        __syncthreads();
    }

    // epilogue: 2 i-halves x 4 o; lanes along i -> 128B coalesced stores
    #pragma unroll
    for (int j = 0; j < 2; j++) {
        const int i = iBase + j * 32 + tx;
        #pragma unroll
        for (int c = 0; c < 2; c++) {
            #pragma unroll
            for (int h = 0; h < 2; h++) {
                int o = oBase + wp * 4 + c * 2 + h;
                size_t off = (size_t)o * IN_ + i;
                outW[off] = W[off] + accf[j][c][h] * A_SC;
            }
        }
    }
}

// ---------------------------------------------------------------------------
extern "C" void kernel_launch(void* const* d_in, const int* in_sizes, int n_in,
                              void* d_out, int out_size)
{
    const float* spikes   = (const float*)d_in[0];
    const float* W        = (const float*)d_in[1];
    const float* membrane = (const float*)d_in[2];
    const float* dpre     = (const float*)d_in[3];
    const float* dfire    = (const float*)d_in[4];

    float* out       = (float*)d_out;
    float* out_spike = out;                                   // (B, OUT)
    float* out_W     = out + B_ * OUT_;                       // (OUT, IN)
    float* out_mem   = out + B_ * OUT_ + (size_t)OUT_ * IN_;  // (B, OUT)

    k_front<<<1536, 256>>>(W, spikes, dpre);
    k_matmul<<<dim3(16, 16), 256>>>(spikes);
    k_lif<<<(B_ * OUT_ / 2) / 256, 256>>>(membrane, dfire, out_spike, out_mem);
    k_stdp<<<dim3(32, 16), 256>>>(W, out_W);
}

// round 7
// speedup vs baseline: 2.2914x; 1.2010x over previous
#include <cuda_runtime.h>
#include <cuda_fp16.h>

#define B_    128
#define IN_   1024
#define OUT_  1024

constexpr float BETA    = 0.99f;
constexpr float THRESH  = 1.0f;
constexpr float RESETV  = 0.8f;
constexpr float INV_TAU = 0.05f;              // 1/20
constexpr float A_SC    = 0.005f / 128.0f;    // A / B

// ---- device scratch (static, allocation-free) ------------------------------
__device__ float g_Wt[IN_ * OUT_];            // Wt[k][o] = W[o][k]
__device__ float g_weighted[B_ * OUT_];       // spikes @ W^T
__device__ int   g_sIdx[B_ * 256];            // spiking-k indices per batch (ordered)
__device__ int   g_sCnt[B_];
// Ipk slot layout: within each 64-i group g, i=(g*64+r) stored at slot
// g*64 + (r&31)*2 + (r>>5)  ->  (i, i+32) adjacent uint2 = one uint4.
__device__ uint2 g_Ipk[B_ * IN_];             // (p2, q2): e^{+dp/20}, e^{-dp/20}
__device__ uint2 g_Opk[B_ * OUT_ / 2];        // per o-pair (r2, -s2)

__device__ __forceinline__ __half2 u2h(unsigned u) { return *reinterpret_cast<__half2*>(&u); }
__device__ __forceinline__ unsigned h2u(__half2 h) { return *reinterpret_cast<unsigned*>(&h); }

// ---------------------------------------------------------------------------
// Front kernel: [0,1024) transpose W -> Wt; [1024,1536) Ipack;
//               [1536,1664) spike-index compaction (order-preserving).
// ---------------------------------------------------------------------------
__global__ __launch_bounds__(256) void k_front(
    const float* __restrict__ W,
    const float* __restrict__ spikes,
    const float* __restrict__ dpre)
{
    if (blockIdx.x < 1024) {
        __shared__ float t[32][33];
        const int bx = (blockIdx.x & 31) * 32;   // k range
        const int by = (blockIdx.x >> 5) * 32;   // o range
        const int tx = threadIdx.x & 31;
        const int ty = threadIdx.x >> 5;         // 0..7
        #pragma unroll
        for (int i = 0; i < 32; i += 8)
            t[ty + i][tx] = W[(size_t)(by + ty + i) * IN_ + bx + tx];
        __syncthreads();
        #pragma unroll
        for (int i = 0; i < 32; i += 8)
            g_Wt[(size_t)(bx + ty + i) * OUT_ + by + tx] = t[tx][ty + i];
    } else if (blockIdx.x < 1536) {
        int idx = (blockIdx.x - 1024) * 256 + threadIdx.x;  // b*IN_ + i
        float dp = (spikes[idx] > 0.0f) ? 0.0f : dpre[idx] + 1.0f;
        uint2 u;
        u.x = h2u(__float2half2_rn(__expf(dp * INV_TAU)));   // p pair
        u.y = h2u(__float2half2_rn(__expf(-dp * INV_TAU)));  // q pair
        int i = idx & (IN_ - 1);
        int b = idx >> 10;
        int g = i >> 6, r = i & 63;
        int slot = (g << 6) + ((r & 31) << 1) + (r >> 5);
        g_Ipk[b * IN_ + slot] = u;
    } else {
        // spike-index compaction for batch b (deterministic, order-preserving)
        __shared__ int wsum[8];
        __shared__ int wbase[8];
        const int b = blockIdx.x - 1536;
        const int tid = threadIdx.x;
        const int lane = tid & 31, wid = tid >> 5;

        float4 sp = reinterpret_cast<const float4*>(spikes)[b * 256 + tid];
        int f0 = sp.x > 0.0f, f1 = sp.y > 0.0f, f2 = sp.z > 0.0f, f3 = sp.w > 0.0f;
        int c = f0 + f1 + f2 + f3;

        int s = c;                                 // inclusive warp scan
        #pragma unroll
        for (int d = 1; d < 32; d <<= 1) {
            int v = __shfl_up_sync(0xFFFFFFFFu, s, d);
            if (lane >= d) s += v;
        }
        if (lane == 31) wsum[wid] = s;
        __syncthreads();
        if (tid == 0) {
            int acc = 0;
            #pragma unroll
            for (int w = 0; w < 8; w++) { wbase[w] = acc; acc += wsum[w]; }
            g_sCnt[b] = acc;
        }
        __syncthreads();

        int base = wbase[wid] + (s - c);           // exclusive offset
        int k0 = tid * 4;
        int* dst = &g_sIdx[b * 256];
        if (f0) dst[base++] = k0;
        if (f1) dst[base++] = k0 + 1;
        if (f2) dst[base++] = k0 + 2;
        if (f3) dst[base  ] = k0 + 3;
    }
}

// ---------------------------------------------------------------------------
// Sparse matmul: weighted[b, o] = sum_{k in spike list} Wt[k][o].
// grid (4 o-chunks of 256, 128 b). 256 threads, thread = one o.
// ---------------------------------------------------------------------------
__global__ __launch_bounds__(256) void k_matmulS()
{
    __shared__ int sk[256];
    const int tid = threadIdx.x;
    const int b = blockIdx.y;
    const int o = blockIdx.x * 256 + tid;

    const int cnt = g_sCnt[b];
    if (tid < cnt) sk[tid] = g_sIdx[b * 256 + tid];
    __syncthreads();

    float a0 = 0.f, a1 = 0.f, a2 = 0.f, a3 = 0.f;
    int j = 0;
    for (; j + 4 <= cnt; j += 4) {
        int k0 = sk[j], k1 = sk[j + 1], k2 = sk[j + 2], k3 = sk[j + 3];
        a0 += g_Wt[(size_t)k0 * OUT_ + o];
        a1 += g_Wt[(size_t)k1 * OUT_ + o];
        a2 += g_Wt[(size_t)k2 * OUT_ + o];
        a3 += g_Wt[(size_t)k3 * OUT_ + o];
    }
    for (; j < cnt; j++)
        a0 += g_Wt[(size_t)sk[j] * OUT_ + o];

    g_weighted[b * OUT_ + o] = (a0 + a1) + (a2 + a3);
}

// ---------------------------------------------------------------------------
// LIF: membrane update, threshold/reset, spike+mem out, Opack (uint2/pair).
// ---------------------------------------------------------------------------
__global__ __launch_bounds__(256) void k_lif(
    const float* __restrict__ membrane, const float* __restrict__ dfire,
    float* __restrict__ out_spike, float* __restrict__ out_mem)
{
    int idx = blockIdx.x * 256 + threadIdx.x;     // B_*OUT_/2
    int b = idx >> 9, opi = idx & 511;
    int base = b * OUT_ + opi * 2;

    float2 wv  = *reinterpret_cast<const float2*>(&g_weighted[base]);
    float2 mem = *reinterpret_cast<const float2*>(&membrane[base]);
    float2 dfr = *reinterpret_cast<const float2*>(&dfire[base]);

    float m0 = mem.x * BETA + wv.x, m1 = mem.y * BETA + wv.y;
    float s0 = (m0 > THRESH) ? 1.0f : 0.0f;
    float s1 = (m1 > THRESH) ? 1.0f : 0.0f;
    if (s0 > 0.f) m0 -= RESETV;
    if (s1 > 0.f) m1 -= RESETV;

    *reinterpret_cast<float2*>(&out_spike[base]) = make_float2(s0, s1);
    *reinterpret_cast<float2*>(&out_mem[base])   = make_float2(m0, m1);

    float df0 = (s0 > 0.f) ? 0.0f : dfr.x + 1.0f;
    float df1 = (s1 > 0.f) ? 0.0f : dfr.y + 1.0f;
    uint2 u;
    u.x = h2u(__floats2half2_rn(__expf(-df0 * INV_TAU), __expf(-df1 * INV_TAU)));  // r
    u.y = h2u(__floats2half2_rn(-__expf(df0 * INV_TAU), -__expf(df1 * INV_TAU))); // -s
    g_Opk[b * (OUT_ / 2) + opi] = u;
}

// ---------------------------------------------------------------------------
// STDP via product-vs-1 test (exact at dp==df):
//   t1 = p*r < 1  <=> df > dp : contribute +t1
//   t2 = q*(-s) > -1 <=> df < dp : contribute t2
// Tile 64i x 16o, grid (64 o-blk, 16 i-blk) = 1024 blocks, 128 threads.
// Thread: 2 i (one interleaved uint4) x 4 o (one uint4 broadcast).
// ---------------------------------------------------------------------------
__global__ __launch_bounds__(128) void k_stdp(
    const float* __restrict__ W, float* __restrict__ outW)
{
    __shared__ uint4 sI[16][32];   // 8 KB: (p,q) for i=j and i=j+32
    __shared__ uint4 sO[16][4];    // 1 KB: o-quads

    const int tid = threadIdx.x;
    const int tx = tid & 31;       // lane -> i (and i+32)
    const int wp = tid >> 5;       // warp (0..3) -> o-quad
    const int oBase = blockIdx.x * 16;
    const int iBase = blockIdx.y * 64;

    const __half2 ONE  = __float2half2_rn(1.0f);
    const __half2 NEG1 = __float2half2_rn(-1.0f);

    float accf[2][2][2];           // [i-half][o-pair][lo/hi]
    #pragma unroll
    for (int j = 0; j < 2; j++)
        #pragma unroll
        for (int c = 0; c < 2; c++) { accf[j][c][0] = 0.f; accf[j][c][1] = 0.f; }

    const uint4* Ipk4 = reinterpret_cast<const uint4*>(g_Ipk);
    const uint4* Opk4 = reinterpret_cast<const uint4*>(g_Opk);

    for (int cb = 0; cb < 8; cb++) {           // 8 chunks of 16 batches
        // sI: 16 b x 32 uint4 = 512; 4 per thread, coalesced LDG.128
        #pragma unroll
        for (int t = tid; t < 512; t += 128) {
            int b = t >> 5, j = t & 31;
            sI[b][j] = Ipk4[((cb * 16 + b) * IN_ + iBase) / 2 + j];
        }
        // sO: 16 b x 4 uint4 = 64
        if (tid < 64) {
            int b = tid >> 2, j = tid & 3;
            sO[b][j] = Opk4[(cb * 16 + b) * (OUT_ / 4) + (oBase >> 2) + j];
        }
        __syncthreads();

        __half2 acch[2][2];
        #pragma unroll
        for (int j = 0; j < 2; j++) {
            acch[j][0] = __float2half2_rn(0.f);
            acch[j][1] = __float2half2_rn(0.f);
        }

        #pragma unroll 4
        for (int b = 0; b < 16; b++) {
            uint4 iv = sI[b][tx];              // LDS.128 conflict-free
            uint4 ov = sO[b][wp];              // LDS.128 broadcast
            __half2 pq[2][2] = {{u2h(iv.x), u2h(iv.y)}, {u2h(iv.z), u2h(iv.w)}};
            __half2 rs[2][2] = {{u2h(ov.x), u2h(ov.y)}, {u2h(ov.z), u2h(ov.w)}};
            #pragma unroll
            for (int j = 0; j < 2; j++) {      // i-half
                #pragma unroll
                for (int c = 0; c < 2; c++) {  // o-pair
                    __half2 t1 = __hmul2(pq[j][0], rs[c][0]);
                    __half2 t2 = __hmul2(pq[j][1], rs[c][1]);
                    __half2 m1 = __hlt2(t1, ONE);
                    __half2 m2 = __hgt2(t2, NEG1);
                    acch[j][c] = __hfma2(m1, t1, acch[j][c]);
                    acch[j][c] = __hfma2(m2, t2, acch[j][c]);
                }
            }
        }

        #pragma unroll
        for (int j = 0; j < 2; j++)
            #pragma unroll
            for (int c = 0; c < 2; c++) {
                accf[j][c][0] += __low2float(acch[j][c]);
                accf[j][c][1] += __high2float(acch[j][c]);
            }
        __syncthreads();
    }

    // epilogue: lanes along i -> 128B coalesced stores
    #pragma unroll
    for (int j = 0; j < 2; j++) {
        const int i = iBase + j * 32 + tx;
        #pragma unroll
        for (int c = 0; c < 2; c++) {
            #pragma unroll
            for (int h = 0; h < 2; h++) {
                int o = oBase + wp * 4 + c * 2 + h;
                size_t off = (size_t)o * IN_ + i;
                outW[off] = W[off] + accf[j][c][h] * A_SC;
            }
        }
    }
}

// ---------------------------------------------------------------------------
extern "C" void kernel_launch(void* const* d_in, const int* in_sizes, int n_in,
                              void* d_out, int out_size)
{
    const float* spikes   = (const float*)d_in[0];
    const float* W        = (const float*)d_in[1];
    const float* membrane = (const float*)d_in[2];
    const float* dpre     = (const float*)d_in[3];
    const float* dfire    = (const float*)d_in[4];

    float* out       = (float*)d_out;
    float* out_spike = out;                                   // (B, OUT)
    float* out_W     = out + B_ * OUT_;                       // (OUT, IN)
    float* out_mem   = out + B_ * OUT_ + (size_t)OUT_ * IN_;  // (B, OUT)

    k_front<<<1664, 256>>>(W, spikes, dpre);
    k_matmulS<<<dim3(4, 128), 256>>>();
    k_lif<<<(B_ * OUT_ / 2) / 256, 256>>>(membrane, dfire, out_spike, out_mem);
    k_stdp<<<dim3(64, 16), 128>>>(W, out_W);
}

// round 8
// speedup vs baseline: 2.4307x; 1.0608x over previous
#include <cuda_runtime.h>
#include <cuda_fp16.h>

#define B_    128
#define IN_   1024
#define OUT_  1024

constexpr float BETA    = 0.99f;
constexpr float THRESH  = 1.0f;
constexpr float RESETV  = 0.8f;
constexpr float INV_TAU = 0.05f;              // 1/20
constexpr float A_SC    = 0.005f / 128.0f;    // A / B

// ---- device scratch (static, allocation-free) ------------------------------
__device__ float g_Wt[IN_ * OUT_];            // Wt[k][o] = W[o][k]
__device__ int   g_sIdx[B_ * 256];            // spiking-k indices per batch (ordered)
__device__ int   g_sCnt[B_];
// Ipk slot layout: within each 64-i group g, i=(g*64+r) stored at slot
// g*64 + (r&31)*2 + (r>>5)  ->  (i, i+32) adjacent uint2 = one uint4.
__device__ uint2 g_Ipk[B_ * IN_];             // (p2, q2): e^{+dp/20}, e^{-dp/20}
__device__ uint2 g_Opk[B_ * OUT_ / 2];        // per o-pair (r2, -s2)

__device__ __forceinline__ __half2 u2h(unsigned u) { return *reinterpret_cast<__half2*>(&u); }
__device__ __forceinline__ unsigned h2u(__half2 h) { return *reinterpret_cast<unsigned*>(&h); }

// ---------------------------------------------------------------------------
// Front kernel: [0,1024) transpose W -> Wt; [1024,1536) Ipack;
//               [1536,1664) spike-index compaction (order-preserving).
// ---------------------------------------------------------------------------
__global__ __launch_bounds__(256) void k_front(
    const float* __restrict__ W,
    const float* __restrict__ spikes,
    const float* __restrict__ dpre)
{
    if (blockIdx.x < 1024) {
        __shared__ float t[32][33];
        const int bx = (blockIdx.x & 31) * 32;   // k range
        const int by = (blockIdx.x >> 5) * 32;   // o range
        const int tx = threadIdx.x & 31;
        const int ty = threadIdx.x >> 5;         // 0..7
        #pragma unroll
        for (int i = 0; i < 32; i += 8)
            t[ty + i][tx] = W[(size_t)(by + ty + i) * IN_ + bx + tx];
        __syncthreads();
        #pragma unroll
        for (int i = 0; i < 32; i += 8)
            g_Wt[(size_t)(bx + ty + i) * OUT_ + by + tx] = t[tx][ty + i];
    } else if (blockIdx.x < 1536) {
        int idx = (blockIdx.x - 1024) * 256 + threadIdx.x;  // b*IN_ + i
        float dp = (spikes[idx] > 0.0f) ? 0.0f : dpre[idx] + 1.0f;
        uint2 u;
        u.x = h2u(__float2half2_rn(__expf(dp * INV_TAU)));   // p pair
        u.y = h2u(__float2half2_rn(__expf(-dp * INV_TAU)));  // q pair
        int i = idx & (IN_ - 1);
        int b = idx >> 10;
        int g = i >> 6, r = i & 63;
        int slot = (g << 6) + ((r & 31) << 1) + (r >> 5);
        g_Ipk[b * IN_ + slot] = u;
    } else {
        // spike-index compaction for batch b (deterministic, order-preserving)
        __shared__ int wsum[8];
        __shared__ int wbase[8];
        const int b = blockIdx.x - 1536;
        const int tid = threadIdx.x;
        const int lane = tid & 31, wid = tid >> 5;

        float4 sp = reinterpret_cast<const float4*>(spikes)[b * 256 + tid];
        int f0 = sp.x > 0.0f, f1 = sp.y > 0.0f, f2 = sp.z > 0.0f, f3 = sp.w > 0.0f;
        int c = f0 + f1 + f2 + f3;

        int s = c;                                 // inclusive warp scan
        #pragma unroll
        for (int d = 1; d < 32; d <<= 1) {
            int v = __shfl_up_sync(0xFFFFFFFFu, s, d);
            if (lane >= d) s += v;
        }
        if (lane == 31) wsum[wid] = s;
        __syncthreads();
        if (tid == 0) {
            int acc = 0;
            #pragma unroll
            for (int w = 0; w < 8; w++) { wbase[w] = acc; acc += wsum[w]; }
            g_sCnt[b] = acc;
        }
        __syncthreads();

        int base = wbase[wid] + (s - c);           // exclusive offset
        int k0 = tid * 4;
        int* dst = &g_sIdx[b * 256];
        if (f0) dst[base++] = k0;
        if (f1) dst[base++] = k0 + 1;
        if (f2) dst[base++] = k0 + 2;
        if (f3) dst[base  ] = k0 + 3;
    }
}

// ---------------------------------------------------------------------------
// Fused sparse matmul + LIF + Opack.
// grid (4 o-chunks of 256, 128 b). 256 threads, thread = one o.
// ---------------------------------------------------------------------------
__global__ __launch_bounds__(256) void k_mm_lif(
    const float* __restrict__ membrane, const float* __restrict__ dfire,
    float* __restrict__ out_spike, float* __restrict__ out_mem)
{
    __shared__ int sk[256];
    const int tid = threadIdx.x;
    const int b = blockIdx.y;
    const int o = blockIdx.x * 256 + tid;

    const int cnt = g_sCnt[b];
    if (tid < cnt) sk[tid] = g_sIdx[b * 256 + tid];
    __syncthreads();

    float a0 = 0.f, a1 = 0.f, a2 = 0.f, a3 = 0.f;
    int j = 0;
    for (; j + 4 <= cnt; j += 4) {
        int k0 = sk[j], k1 = sk[j + 1], k2 = sk[j + 2], k3 = sk[j + 3];
        a0 += g_Wt[(size_t)k0 * OUT_ + o];
        a1 += g_Wt[(size_t)k1 * OUT_ + o];
        a2 += g_Wt[(size_t)k2 * OUT_ + o];
        a3 += g_Wt[(size_t)k3 * OUT_ + o];
    }
    for (; j < cnt; j++)
        a0 += g_Wt[(size_t)sk[j] * OUT_ + o];
    float wsum = (a0 + a1) + (a2 + a3);

    const int base = b * OUT_ + o;
    float m = membrane[base] * BETA + wsum;
    float sp = (m > THRESH) ? 1.0f : 0.0f;
    if (sp > 0.f) m -= RESETV;
    out_spike[base] = sp;
    out_mem[base]   = m;

    float df = (sp > 0.f) ? 0.0f : dfire[base] + 1.0f;
    float r  = __expf(-df * INV_TAU);
    float ns = -__expf(df * INV_TAU);
    float r1  = __shfl_xor_sync(0xFFFFFFFFu, r, 1);
    float ns1 = __shfl_xor_sync(0xFFFFFFFFu, ns, 1);
    if (!(o & 1)) {
        uint2 u;
        u.x = h2u(__floats2half2_rn(r, r1));    // (r_o, r_o+1)
        u.y = h2u(__floats2half2_rn(ns, ns1));  // (-s_o, -s_o+1)
        g_Opk[base >> 1] = u;
    }
}

// ---------------------------------------------------------------------------
// STDP via product-vs-1 test (exact at dp==df):
//   t1 = p*r < 1  <=> df > dp : contribute +t1
//   t2 = q*(-s) > -1 <=> df < dp : contribute t2
// Tile 64i x 16o, grid (64 o-blk, 16 i-blk) = 1024 blocks, 128 threads.
// Inner b-loop register-prefetched one iteration ahead (hides LDS latency).
// ---------------------------------------------------------------------------
__global__ __launch_bounds__(128) void k_stdp(
    const float* __restrict__ W, float* __restrict__ outW)
{
    __shared__ uint4 sI[16][32];   // 8 KB: (p,q) for i=j and i=j+32
    __shared__ uint4 sO[16][4];    // 1 KB: o-quads

    const int tid = threadIdx.x;
    const int tx = tid & 31;       // lane -> i (and i+32)
    const int wp = tid >> 5;       // warp (0..3) -> o-quad
    const int oBase = blockIdx.x * 16;
    const int iBase = blockIdx.y * 64;

    const __half2 ONE  = __float2half2_rn(1.0f);
    const __half2 NEG1 = __float2half2_rn(-1.0f);

    float accf[2][2][2];           // [i-half][o-pair][lo/hi]
    #pragma unroll
    for (int j = 0; j < 2; j++)
        #pragma unroll
        for (int c = 0; c < 2; c++) { accf[j][c][0] = 0.f; accf[j][c][1] = 0.f; }

    const uint4* Ipk4 = reinterpret_cast<const uint4*>(g_Ipk);
    const uint4* Opk4 = reinterpret_cast<const uint4*>(g_Opk);

    for (int cb = 0; cb < 8; cb++) {           // 8 chunks of 16 batches
        // sI: 16 b x 32 uint4 = 512; 4 per thread, coalesced LDG.128
        #pragma unroll
        for (int t = tid; t < 512; t += 128) {
            int b = t >> 5, j = t & 31;
            sI[b][j] = Ipk4[((cb * 16 + b) * IN_ + iBase) / 2 + j];
        }
        // sO: 16 b x 4 uint4 = 64
        if (tid < 64) {
            int b = tid >> 2, j = tid & 3;
            sO[b][j] = Opk4[(cb * 16 + b) * (OUT_ / 4) + (oBase >> 2) + j];
        }
        __syncthreads();

        __half2 acch[2][2];
        #pragma unroll
        for (int j = 0; j < 2; j++) {
            acch[j][0] = __float2half2_rn(0.f);
            acch[j][1] = __float2half2_rn(0.f);
        }

        // software-pipelined: prefetch b+1 while computing b
        uint4 iv = sI[0][tx];
        uint4 ov = sO[0][wp];
        #pragma unroll
        for (int b = 0; b < 16; b++) {
            uint4 ivn, ovn;
            if (b < 15) {
                ivn = sI[b + 1][tx];           // LDS.128 conflict-free
                ovn = sO[b + 1][wp];           // LDS.128 broadcast
            }
            __half2 pq[2][2] = {{u2h(iv.x), u2h(iv.y)}, {u2h(iv.z), u2h(iv.w)}};
            __half2 rs[2][2] = {{u2h(ov.x), u2h(ov.y)}, {u2h(ov.z), u2h(ov.w)}};
            #pragma unroll
            for (int j = 0; j < 2; j++) {      // i-half
                #pragma unroll
                for (int c = 0; c < 2; c++) {  // o-pair
                    __half2 t1 = __hmul2(pq[j][0], rs[c][0]);
                    __half2 t2 = __hmul2(pq[j][1], rs[c][1]);
                    __half2 m1 = __hlt2(t1, ONE);
                    __half2 m2 = __hgt2(t2, NEG1);
                    acch[j][c] = __hfma2(m1, t1, acch[j][c]);
                    acch[j][c] = __hfma2(m2, t2, acch[j][c]);
                }
            }
            iv = ivn; ov = ovn;
        }

        #pragma unroll
        for (int j = 0; j < 2; j++)
            #pragma unroll
            for (int c = 0; c < 2; c++) {
                accf[j][c][0] += __low2float(acch[j][c]);
                accf[j][c][1] += __high2float(acch[j][c]);
            }
        __syncthreads();
    }

    // epilogue: lanes along i -> 128B coalesced stores
    #pragma unroll
    for (int j = 0; j < 2; j++) {
        const int i = iBase + j * 32 + tx;
        #pragma unroll
        for (int c = 0; c < 2; c++) {
            #pragma unroll
            for (int h = 0; h < 2; h++) {
                int o = oBase + wp * 4 + c * 2 + h;
                size_t off = (size_t)o * IN_ + i;
                outW[off] = W[off] + accf[j][c][h] * A_SC;
            }
        }
    }
}

// ---------------------------------------------------------------------------
extern "C" void kernel_launch(void* const* d_in, const int* in_sizes, int n_in,
                              void* d_out, int out_size)
{
    const float* spikes   = (const float*)d_in[0];
    const float* W        = (const float*)d_in[1];
    const float* membrane = (const float*)d_in[2];
    const float* dpre     = (const float*)d_in[3];
    const float* dfire    = (const float*)d_in[4];

    float* out       = (float*)d_out;
    float* out_spike = out;                                   // (B, OUT)
    float* out_W     = out + B_ * OUT_;                       // (OUT, IN)
    float* out_mem   = out + B_ * OUT_ + (size_t)OUT_ * IN_;  // (B, OUT)

    k_front<<<1664, 256>>>(W, spikes, dpre);
    k_mm_lif<<<dim3(4, 128), 256>>>(membrane, dfire, out_spike, out_mem);
    k_stdp<<<dim3(64, 16), 128>>>(W, out_W);
}